// round 2
// baseline (speedup 1.0000x reference)
#include <cuda_runtime.h>

// LinearAttention: B=16, DK=64, N=8192, DV=64, fp32.
//   ktv[b,k,j] = sum_n k[b,n,k] * v[b,n,j]
//   out[b,n,j] = sum_k q[b,k,n] * ktv[b,k,j]
// Inputs (metadata order): q [B,DK,N], k [B,N,DK], v [B,N,DV]. Output [B,N,DV] fp32.

#define BATCH 16
#define DKC   64
#define NSEQ  8192
#define DVC   64
#define S1    64            // phase-1 N-splits
#define CHUNK (NSEQ / S1)   // 128 rows per phase-1 block

// Scratch (device globals; no allocation at runtime).
__device__ float g_part[BATCH * S1 * DKC * DVC];  // 16 MB partial ktv
__device__ float g_ktv [BATCH * DKC * DVC];       // 256 KB reduced ktv

// ---- packed f32x2 helpers (Blackwell FFMA2 via PTX) ----
__device__ __forceinline__ unsigned long long pack2(float x) {
    unsigned long long r;
    asm("mov.b64 %0, {%1, %1};" : "=l"(r) : "f"(x));
    return r;
}
__device__ __forceinline__ void ffma2(unsigned long long& d,
                                      unsigned long long a,
                                      unsigned long long b) {
    asm("fma.rn.f32x2 %0, %1, %2, %0;" : "+l"(d) : "l"(a), "l"(b));
}

// ============================================================================
// Phase 1: partial ktv = k_chunk^T @ v_chunk  (per (batch, split))
// Block: 128 threads. Each thread owns a 4(k-rows) x 8(v-cols) tile of the
// 64x64 output -> 16 FFMA2 per n-step.
// ============================================================================
__global__ __launch_bounds__(128) void phase1_kernel(
    const float* __restrict__ kmat, const float* __restrict__ vmat)
{
    __shared__ float ks[64 * 64];
    __shared__ float vs[64 * 64];

    const int b = blockIdx.y;
    const int s = blockIdx.x;
    const int t = threadIdx.x;

    const int kg = t >> 3;          // 0..15
    const int jg = t & 7;           // 0..7
    const int k0 = kg * 4;
    const int j0 = jg * 8;

    unsigned long long acc[4][4];
#pragma unroll
    for (int i = 0; i < 4; i++)
#pragma unroll
        for (int p = 0; p < 4; p++) acc[i][p] = 0ULL;

    const long base = ((long)b * NSEQ + (long)s * CHUNK) * DKC;

    for (int sub = 0; sub < CHUNK; sub += 64) {
        const float4* kg4 = (const float4*)(kmat + base + (long)sub * DKC);
        const float4* vg4 = (const float4*)(vmat + base + (long)sub * DVC);
        __syncthreads();
#pragma unroll
        for (int i = 0; i < 8; i++) {
            int idx = t + i * 128;                // 1024 float4 per tile
            ((float4*)ks)[idx] = kg4[idx];
            ((float4*)vs)[idx] = vg4[idx];
        }
        __syncthreads();

#pragma unroll 4
        for (int n = 0; n < 64; n++) {
            float4 kk = *(const float4*)(ks + n * 64 + k0);
            ulonglong2 va = *(const ulonglong2*)(vs + n * 64 + j0);
            ulonglong2 vb = *(const ulonglong2*)(vs + n * 64 + j0 + 4);
            unsigned long long kd0 = pack2(kk.x);
            unsigned long long kd1 = pack2(kk.y);
            unsigned long long kd2 = pack2(kk.z);
            unsigned long long kd3 = pack2(kk.w);
            ffma2(acc[0][0], kd0, va.x); ffma2(acc[0][1], kd0, va.y);
            ffma2(acc[0][2], kd0, vb.x); ffma2(acc[0][3], kd0, vb.y);
            ffma2(acc[1][0], kd1, va.x); ffma2(acc[1][1], kd1, va.y);
            ffma2(acc[1][2], kd1, vb.x); ffma2(acc[1][3], kd1, vb.y);
            ffma2(acc[2][0], kd2, va.x); ffma2(acc[2][1], kd2, va.y);
            ffma2(acc[2][2], kd2, vb.x); ffma2(acc[2][3], kd2, vb.y);
            ffma2(acc[3][0], kd3, va.x); ffma2(acc[3][1], kd3, va.y);
            ffma2(acc[3][2], kd3, vb.x); ffma2(acc[3][3], kd3, vb.y);
        }
    }

    float* p = g_part + ((long)(b * S1 + s)) * (DKC * DVC);
#pragma unroll
    for (int i = 0; i < 4; i++) {
        float* row = p + (k0 + i) * DVC + j0;
        *(ulonglong2*)(row)     = make_ulonglong2(acc[i][0], acc[i][1]);
        *(ulonglong2*)(row + 4) = make_ulonglong2(acc[i][2], acc[i][3]);
    }
}

// ============================================================================
// Phase 1b: reduce S1 partials -> g_ktv
// ============================================================================
__global__ __launch_bounds__(256) void reduce_kernel()
{
    const int o = blockIdx.x * 256 + threadIdx.x;   // 0..65535
    const int b = o >> 12;
    const int r = o & 4095;
    const float* p = g_part + (long)b * S1 * 4096 + r;
    float s = 0.f;
#pragma unroll
    for (int i = 0; i < S1; i++) s += p[i * 4096];
    g_ktv[o] = s;
}

// ============================================================================
// Phase 2: out[b,n,:] = q[b,:,n]^T @ ktv[b]
// Block: 256 threads over a 256-row n-chunk. Thread tile: 4 n x 16 j.
// Per k-step: 1 LDG.128 (q, coalesced) + 4 LDS.128 (ktv, broadcast) + 32 FFMA2.
// ============================================================================
__global__ __launch_bounds__(256) void phase2_kernel(
    const float* __restrict__ q, float* __restrict__ out)
{
    __shared__ float ktvs[DKC * DVC];

    const int b = blockIdx.y;
    const int t = threadIdx.x;

    const float4* src = (const float4*)(g_ktv + b * (DKC * DVC));
#pragma unroll
    for (int i = 0; i < 4; i++)
        ((float4*)ktvs)[t + i * 256] = src[t + i * 256];
    __syncthreads();

    const int ng = t & 63;          // 0..63
    const int jg = t >> 6;          // 0..3
    const int n0 = blockIdx.x * 256 + ng * 4;
    const int j0 = jg * 16;

    unsigned long long acc[4][8];
#pragma unroll
    for (int i = 0; i < 4; i++)
#pragma unroll
        for (int p = 0; p < 8; p++) acc[i][p] = 0ULL;

    const float* qp = q + (long)b * DKC * NSEQ + n0;

#pragma unroll 4
    for (int kk = 0; kk < DKC; kk++) {
        float4 q4 = *(const float4*)(qp + (long)kk * NSEQ);
        ulonglong2 p0 = *(const ulonglong2*)(ktvs + kk * 64 + j0);
        ulonglong2 p1 = *(const ulonglong2*)(ktvs + kk * 64 + j0 + 4);
        ulonglong2 p2 = *(const ulonglong2*)(ktvs + kk * 64 + j0 + 8);
        ulonglong2 p3 = *(const ulonglong2*)(ktvs + kk * 64 + j0 + 12);
        unsigned long long qd0 = pack2(q4.x);
        unsigned long long qd1 = pack2(q4.y);
        unsigned long long qd2 = pack2(q4.z);
        unsigned long long qd3 = pack2(q4.w);

        ffma2(acc[0][0], qd0, p0.x); ffma2(acc[0][1], qd0, p0.y);
        ffma2(acc[0][2], qd0, p1.x); ffma2(acc[0][3], qd0, p1.y);
        ffma2(acc[0][4], qd0, p2.x); ffma2(acc[0][5], qd0, p2.y);
        ffma2(acc[0][6], qd0, p3.x); ffma2(acc[0][7], qd0, p3.y);

        ffma2(acc[1][0], qd1, p0.x); ffma2(acc[1][1], qd1, p0.y);
        ffma2(acc[1][2], qd1, p1.x); ffma2(acc[1][3], qd1, p1.y);
        ffma2(acc[1][4], qd1, p2.x); ffma2(acc[1][5], qd1, p2.y);
        ffma2(acc[1][6], qd1, p3.x); ffma2(acc[1][7], qd1, p3.y);

        ffma2(acc[2][0], qd2, p0.x); ffma2(acc[2][1], qd2, p0.y);
        ffma2(acc[2][2], qd2, p1.x); ffma2(acc[2][3], qd2, p1.y);
        ffma2(acc[2][4], qd2, p2.x); ffma2(acc[2][5], qd2, p2.y);
        ffma2(acc[2][6], qd2, p3.x); ffma2(acc[2][7], qd2, p3.y);

        ffma2(acc[3][0], qd3, p0.x); ffma2(acc[3][1], qd3, p0.y);
        ffma2(acc[3][2], qd3, p1.x); ffma2(acc[3][3], qd3, p1.y);
        ffma2(acc[3][4], qd3, p2.x); ffma2(acc[3][5], qd3, p2.y);
        ffma2(acc[3][6], qd3, p3.x); ffma2(acc[3][7], qd3, p3.y);
    }

    float* op = out + ((long)b * NSEQ + n0) * DVC + j0;
#pragma unroll
    for (int i = 0; i < 4; i++) {
        float* row = op + (long)i * DVC;
        *(ulonglong2*)(row)      = make_ulonglong2(acc[i][0], acc[i][1]);
        *(ulonglong2*)(row + 4)  = make_ulonglong2(acc[i][2], acc[i][3]);
        *(ulonglong2*)(row + 8)  = make_ulonglong2(acc[i][4], acc[i][5]);
        *(ulonglong2*)(row + 12) = make_ulonglong2(acc[i][6], acc[i][7]);
    }
}

extern "C" void kernel_launch(void* const* d_in, const int* in_sizes, int n_in,
                              void* d_out, int out_size)
{
    const float* q = (const float*)d_in[0];
    const float* k = (const float*)d_in[1];
    const float* v = (const float*)d_in[2];
    float* out = (float*)d_out;

    phase1_kernel<<<dim3(S1, BATCH), 128>>>(k, v);
    reduce_kernel<<<(BATCH * DKC * DVC) / 256, 256>>>();
    phase2_kernel<<<dim3(NSEQ / 256, BATCH), 256>>>(q, out);
}